// round 3
// baseline (speedup 1.0000x reference)
#include <cuda_runtime.h>
#include <math.h>

#define B_  2
#define S_  4096
#define D_  384
#define H_  6
#define DK  64
#define R_  (B_*S_)
#define EPS 1e-6f

// ---------------- scratch (device globals; no allocation allowed) ----------
__device__ float g_z[R_ * D_];                  // double-LN output
__device__ float g_q[B_ * H_ * S_ * DK];
__device__ float g_k[B_ * H_ * S_ * DK];
__device__ float g_v[B_ * H_ * S_ * DK];
__device__ float g_o[R_ * D_];                  // attention output (pre out-proj)

// ---------------- block reduction (128 threads) ----------------------------
__device__ __forceinline__ float blockSum(float v, float* sh) {
    int tid = threadIdx.x;
#pragma unroll
    for (int o = 16; o > 0; o >>= 1) v += __shfl_xor_sync(0xffffffffu, v, o);
    __syncthreads();                    // protect sh from previous use
    if ((tid & 31) == 0) sh[tid >> 5] = v;
    __syncthreads();
    return sh[0] + sh[1] + sh[2] + sh[3];
}

// ---------------- fused double LayerNorm ------------------------------------
// z = LN(LN(x, ra, rb), a0, b0), torch semantics: unbiased std, /(std+eps)
__global__ __launch_bounds__(128) void ln2_kernel(
    const float* __restrict__ x,
    const float* __restrict__ ra, const float* __restrict__ rb,
    const float* __restrict__ a0, const float* __restrict__ b0)
{
    __shared__ float sh[4];
    int row = blockIdx.x;
    int tid = threadIdx.x;
    const float* xr = x + (size_t)row * D_;

    float v[3];
#pragma unroll
    for (int c = 0; c < 3; c++) v[c] = xr[tid + 128 * c];

    float s = blockSum(v[0] + v[1] + v[2], sh);
    float mean = s * (1.0f / D_);
    float sq = 0.f;
#pragma unroll
    for (int c = 0; c < 3; c++) { float d = v[c] - mean; sq += d * d; }
    sq = blockSum(sq, sh);
    float inv = 1.0f / (sqrtf(sq * (1.0f / (D_ - 1))) + EPS);

    float y[3];
#pragma unroll
    for (int c = 0; c < 3; c++) {
        int i = tid + 128 * c;
        y[c] = ra[i] * (v[c] - mean) * inv + rb[i];
    }

    // second LN
    s = blockSum(y[0] + y[1] + y[2], sh);
    mean = s * (1.0f / D_);
    sq = 0.f;
#pragma unroll
    for (int c = 0; c < 3; c++) { float d = y[c] - mean; sq += d * d; }
    sq = blockSum(sq, sh);
    inv = 1.0f / (sqrtf(sq * (1.0f / (D_ - 1))) + EPS);

    float* zr = g_z + (size_t)row * D_;
#pragma unroll
    for (int c = 0; c < 3; c++) {
        int i = tid + 128 * c;
        zr[i] = a0[i] * (y[c] - mean) * inv + b0[i];
    }
}

// ---------------- QKV projection GEMM ---------------------------------------
// out[r, J] = sum_d z[r,d] * W[J,d] + bias[J], scattered to [b,h,s,dk]
// grid: (R_/64, 1152/64) ; block 256 ; tile 64x64, BK=16, micro 4x4
__global__ __launch_bounds__(256) void gemm_qkv_kernel(
    const float* __restrict__ wq, const float* __restrict__ bq,
    const float* __restrict__ wk, const float* __restrict__ bk,
    const float* __restrict__ wv, const float* __restrict__ bv)
{
    __shared__ float As[16 * 68];   // As[k][m]
    __shared__ float Bs[16 * 68];   // Bs[k][n]

    int m0  = blockIdx.x * 64;
    int n0g = blockIdx.y * 64;                   // 0..1151
    int which = n0g / D_;
    int jrem0 = n0g - which * D_;                // multiple of 64
    const float* W    = (which == 0) ? wq : (which == 1) ? wk : wv;
    const float* bias = (which == 0) ? bq : (which == 1) ? bk : bv;
    float*       Out  = (which == 0) ? g_q : (which == 1) ? g_k : g_v;
    int h = jrem0 / DK;

    int tid = threadIdx.x;
    int tx = tid & 15, ty = tid >> 4;            // n = tx*4+j, m = ty*4+i
    int lrow = tid >> 2, lseg = tid & 3;

    float acc[4][4] = {};
    for (int k0 = 0; k0 < D_; k0 += 16) {
        float4 a4 = *(const float4*)(g_z + (size_t)(m0 + lrow) * D_ + k0 + lseg * 4);
        float4 b4 = *(const float4*)(W + (size_t)(jrem0 + lrow) * D_ + k0 + lseg * 4);
        __syncthreads();
        As[(lseg * 4 + 0) * 68 + lrow] = a4.x;
        As[(lseg * 4 + 1) * 68 + lrow] = a4.y;
        As[(lseg * 4 + 2) * 68 + lrow] = a4.z;
        As[(lseg * 4 + 3) * 68 + lrow] = a4.w;
        Bs[(lseg * 4 + 0) * 68 + lrow] = b4.x;
        Bs[(lseg * 4 + 1) * 68 + lrow] = b4.y;
        Bs[(lseg * 4 + 2) * 68 + lrow] = b4.z;
        Bs[(lseg * 4 + 3) * 68 + lrow] = b4.w;
        __syncthreads();
#pragma unroll
        for (int kk = 0; kk < 16; kk++) {
            float4 av = *(const float4*)&As[kk * 68 + ty * 4];
            float4 bv4 = *(const float4*)&Bs[kk * 68 + tx * 4];
            float ar[4] = {av.x, av.y, av.z, av.w};
            float br[4] = {bv4.x, bv4.y, bv4.z, bv4.w};
#pragma unroll
            for (int i = 0; i < 4; i++)
#pragma unroll
                for (int j = 0; j < 4; j++)
                    acc[i][j] += ar[i] * br[j];
        }
    }
    float4 bb = *(const float4*)(bias + jrem0 + tx * 4);
    float brr[4] = {bb.x, bb.y, bb.z, bb.w};
#pragma unroll
    for (int i = 0; i < 4; i++) {
        int m = m0 + ty * 4 + i;
        int bi = m >> 12;                 // /4096
        int sidx = m & (S_ - 1);
        float4 o;
        o.x = acc[i][0] + brr[0];
        o.y = acc[i][1] + brr[1];
        o.z = acc[i][2] + brr[2];
        o.w = acc[i][3] + brr[3];
        *(float4*)(Out + ((size_t)((bi * H_ + h) * S_ + sidx)) * DK + tx * 4) = o;
    }
}

// ---------------- output projection + residual -------------------------------
// out[r,j] = xres[r,j] + sum_d g_o[r,d]*wo[j,d] + bo[j]
__global__ __launch_bounds__(256) void gemm_out_kernel(
    const float* __restrict__ wo, const float* __restrict__ bo,
    const float* __restrict__ xres, float* __restrict__ out)
{
    __shared__ float As[16 * 68];
    __shared__ float Bs[16 * 68];

    int m0 = blockIdx.x * 64;
    int n0 = blockIdx.y * 64;
    int tid = threadIdx.x;
    int tx = tid & 15, ty = tid >> 4;
    int lrow = tid >> 2, lseg = tid & 3;

    float acc[4][4] = {};
    for (int k0 = 0; k0 < D_; k0 += 16) {
        float4 a4 = *(const float4*)(g_o + (size_t)(m0 + lrow) * D_ + k0 + lseg * 4);
        float4 b4 = *(const float4*)(wo + (size_t)(n0 + lrow) * D_ + k0 + lseg * 4);
        __syncthreads();
        As[(lseg * 4 + 0) * 68 + lrow] = a4.x;
        As[(lseg * 4 + 1) * 68 + lrow] = a4.y;
        As[(lseg * 4 + 2) * 68 + lrow] = a4.z;
        As[(lseg * 4 + 3) * 68 + lrow] = a4.w;
        Bs[(lseg * 4 + 0) * 68 + lrow] = b4.x;
        Bs[(lseg * 4 + 1) * 68 + lrow] = b4.y;
        Bs[(lseg * 4 + 2) * 68 + lrow] = b4.z;
        Bs[(lseg * 4 + 3) * 68 + lrow] = b4.w;
        __syncthreads();
#pragma unroll
        for (int kk = 0; kk < 16; kk++) {
            float4 av = *(const float4*)&As[kk * 68 + ty * 4];
            float4 bv4 = *(const float4*)&Bs[kk * 68 + tx * 4];
            float ar[4] = {av.x, av.y, av.z, av.w};
            float br[4] = {bv4.x, bv4.y, bv4.z, bv4.w};
#pragma unroll
            for (int i = 0; i < 4; i++)
#pragma unroll
                for (int j = 0; j < 4; j++)
                    acc[i][j] += ar[i] * br[j];
        }
    }
    float4 bb = *(const float4*)(bo + n0 + tx * 4);
#pragma unroll
    for (int i = 0; i < 4; i++) {
        int m = m0 + ty * 4 + i;
        float4 xv = *(const float4*)(xres + (size_t)m * D_ + n0 + tx * 4);
        float4 o;
        o.x = xv.x + acc[i][0] + bb.x;
        o.y = xv.y + acc[i][1] + bb.y;
        o.z = xv.z + acc[i][2] + bb.z;
        o.w = xv.w + acc[i][3] + bb.w;
        *(float4*)(out + (size_t)m * D_ + n0 + tx * 4) = o;
    }
}

// ---------------- flash attention ---------------------------------------------
// grid (S_/64, B_*H_), 256 threads. 64q x 64k tiles, online softmax.
// Smem layouts: Qs[d][m], Ks[d][n], Vs[kk][j], Ss[n][m] (then reused as O[m][j]).
#define FL_STRIDE 68
#define FLASH_SMEM_FLOATS (4 * 64 * FL_STRIDE + 3 * 64 + 4 * 64)
#define FLASH_SMEM_BYTES  (FLASH_SMEM_FLOATS * 4)

__global__ __launch_bounds__(256) void flash_kernel()
{
    extern __shared__ float sm[];
    float* Qs = sm;
    float* Ks = Qs + 64 * FL_STRIDE;
    float* Vs = Ks + 64 * FL_STRIDE;
    float* Ss = Vs + 64 * FL_STRIDE;
    float* row_m = Ss + 64 * FL_STRIDE;
    float* row_l = row_m + 64;
    float* row_scale = row_l + 64;
    float* part = row_scale + 64;     // [4][64]

    int bh = blockIdx.y;
    int qb = blockIdx.x;
    const float* Qb = g_q + ((size_t)bh * S_ + qb * 64) * DK;
    const float* Kb = g_k + (size_t)bh * S_ * DK;
    const float* Vb = g_v + (size_t)bh * S_ * DK;

    int tid = threadIdx.x;
    int tx = tid & 15, ty = tid >> 4;     // m = tx*4+i ; (n or j) = ty*4+*
    int lrow = tid >> 2, lseg = tid & 3;
    int sm_m = tid & 63, sm_c = tid >> 6;

    // load Q tile transposed: Qs[d][m]
#pragma unroll
    for (int c2 = 0; c2 < 4; c2++) {
        int d0 = (lseg + c2 * 4) * 4;
        float4 q4 = *(const float4*)(Qb + (size_t)lrow * DK + d0);
        Qs[(d0 + 0) * FL_STRIDE + lrow] = q4.x;
        Qs[(d0 + 1) * FL_STRIDE + lrow] = q4.y;
        Qs[(d0 + 2) * FL_STRIDE + lrow] = q4.z;
        Qs[(d0 + 3) * FL_STRIDE + lrow] = q4.w;
    }
    if (tid < 64) { row_m[tid] = -1e30f; row_l[tid] = 0.f; }

    float acc_o[4][4] = {};

    for (int kt = 0; kt < S_ / 64; kt++) {
        __syncthreads();   // protects Qs (first iter) and Ks/Vs/Ss reuse
        const float* Kt = Kb + (size_t)kt * 64 * DK;
        const float* Vt = Vb + (size_t)kt * 64 * DK;
#pragma unroll
        for (int c2 = 0; c2 < 4; c2++) {
            int d0 = (lseg + c2 * 4) * 4;
            float4 k4 = *(const float4*)(Kt + (size_t)lrow * DK + d0);
            Ks[(d0 + 0) * FL_STRIDE + lrow] = k4.x;
            Ks[(d0 + 1) * FL_STRIDE + lrow] = k4.y;
            Ks[(d0 + 2) * FL_STRIDE + lrow] = k4.z;
            Ks[(d0 + 3) * FL_STRIDE + lrow] = k4.w;
            float4 v4 = *(const float4*)(Vt + (size_t)lrow * DK + d0);
            *(float4*)&Vs[lrow * FL_STRIDE + d0] = v4;
        }
        __syncthreads();

        // S = (Q K^T) * 1/sqrt(dk) ; acc[a][b]: n = ty*4+a, m = tx*4+b
        float acc[4][4] = {};
#pragma unroll 16
        for (int d = 0; d < DK; d++) {
            float4 qv = *(const float4*)&Qs[d * FL_STRIDE + tx * 4];
            float4 kv = *(const float4*)&Ks[d * FL_STRIDE + ty * 4];
            float qr[4] = {qv.x, qv.y, qv.z, qv.w};
            float kr[4] = {kv.x, kv.y, kv.z, kv.w};
#pragma unroll
            for (int a = 0; a < 4; a++)
#pragma unroll
                for (int b = 0; b < 4; b++)
                    acc[a][b] += kr[a] * qr[b];
        }
#pragma unroll
        for (int a = 0; a < 4; a++) {
            float4 sv;
            sv.x = acc[a][0] * 0.125f;
            sv.y = acc[a][1] * 0.125f;
            sv.z = acc[a][2] * 0.125f;
            sv.w = acc[a][3] * 0.125f;
            *(float4*)&Ss[(ty * 4 + a) * FL_STRIDE + tx * 4] = sv;  // Ss[n][m]
        }
        __syncthreads();

        // softmax pass 1: per-row (query) max over this key tile
        {
            float mx = -1e30f;
#pragma unroll
            for (int n2 = 0; n2 < 16; n2++)
                mx = fmaxf(mx, Ss[(sm_c * 16 + n2) * FL_STRIDE + sm_m]);
            part[sm_c * 64 + sm_m] = mx;
        }
        __syncthreads();
        if (tid < 64) {
            float mo = row_m[tid];
            float mx = fmaxf(fmaxf(part[tid], part[64 + tid]),
                             fmaxf(part[128 + tid], part[192 + tid]));
            float mn = fmaxf(mo, mx);
            row_scale[tid] = __expf(mo - mn);
            row_m[tid] = mn;
        }
        __syncthreads();
        // pass 2: exponentiate in place, partial sums
        {
            float mr = row_m[sm_m];
            float ssum = 0.f;
#pragma unroll
            for (int n2 = 0; n2 < 16; n2++) {
                int idx = (sm_c * 16 + n2) * FL_STRIDE + sm_m;
                float p = __expf(Ss[idx] - mr);
                Ss[idx] = p;
                ssum += p;
            }
            part[sm_c * 64 + sm_m] = ssum;
        }
        __syncthreads();
        if (tid < 64)
            row_l[tid] = row_l[tid] * row_scale[tid] +
                         part[tid] + part[64 + tid] + part[128 + tid] + part[192 + tid];
        __syncthreads();

        // rescale O accumulators, then O += P V
#pragma unroll
        for (int i = 0; i < 4; i++) {
            float sc = row_scale[tx * 4 + i];
#pragma unroll
            for (int jj = 0; jj < 4; jj++) acc_o[i][jj] *= sc;
        }
#pragma unroll 16
        for (int kk = 0; kk < 64; kk++) {
            float4 p4 = *(const float4*)&Ss[kk * FL_STRIDE + tx * 4];  // P[kk][m]
            float4 v4 = *(const float4*)&Vs[kk * FL_STRIDE + ty * 4];  // V[kk][j]
            float pr[4] = {p4.x, p4.y, p4.z, p4.w};
            float vr[4] = {v4.x, v4.y, v4.z, v4.w};
#pragma unroll
            for (int i = 0; i < 4; i++)
#pragma unroll
                for (int jj = 0; jj < 4; jj++)
                    acc_o[i][jj] += pr[i] * vr[jj];
        }
    }
    __syncthreads();

    // finalize: O /= l, stage to Ss as [m][j], then coalesced write
#pragma unroll
    for (int i = 0; i < 4; i++) {
        float linv = 1.0f / row_l[tx * 4 + i];
        float4 ov;
        ov.x = acc_o[i][0] * linv;
        ov.y = acc_o[i][1] * linv;
        ov.z = acc_o[i][2] * linv;
        ov.w = acc_o[i][3] * linv;
        *(float4*)&Ss[(tx * 4 + i) * FL_STRIDE + ty * 4] = ov;
    }
    __syncthreads();
    int b = bh / H_, h = bh - b * H_;
    float* Ob = g_o + ((size_t)b * S_ + qb * 64) * D_ + h * DK;
    for (int idx = tid; idx < 64 * 64; idx += 256) {
        int m = idx >> 6, j = idx & 63;
        Ob[(size_t)m * D_ + j] = Ss[m * FL_STRIDE + j];
    }
}

// ---------------- host launcher ----------------------------------------------
extern "C" void kernel_launch(void* const* d_in, const int* in_sizes, int n_in,
                              void* d_out, int out_size)
{
    (void)in_sizes; (void)n_in; (void)out_size;
    const float* x   = (const float*)d_in[0];
    const float* a0  = (const float*)d_in[1];
    const float* b0  = (const float*)d_in[2];
    const float* ra0 = (const float*)d_in[3];
    const float* rb0 = (const float*)d_in[4];
    const float* ra1 = (const float*)d_in[5];
    const float* rb1 = (const float*)d_in[6];
    const float* wq  = (const float*)d_in[7];
    const float* bq  = (const float*)d_in[8];
    const float* wk  = (const float*)d_in[9];
    const float* bk  = (const float*)d_in[10];
    const float* wv  = (const float*)d_in[11];
    const float* bv  = (const float*)d_in[12];
    const float* wo  = (const float*)d_in[13];
    const float* bo  = (const float*)d_in[14];
    float* out = (float*)d_out;

    cudaFuncSetAttribute(flash_kernel,
                         cudaFuncAttributeMaxDynamicSharedMemorySize,
                         FLASH_SMEM_BYTES);

    dim3 gQKV(R_ / 64, (3 * D_) / 64);
    dim3 gOUT(R_ / 64, D_ / 64);
    dim3 gFLA(S_ / 64, B_ * H_);

    // ---- block 1 ----
    ln2_kernel<<<R_, 128>>>(x, ra0, rb0, a0, b0);
    gemm_qkv_kernel<<<gQKV, 256>>>(wq, bq, wk, bk, wv, bv);
    flash_kernel<<<gFLA, 256, FLASH_SMEM_BYTES>>>();
    gemm_out_kernel<<<gOUT, 256>>>(wo, bo, x, out);

    // ---- block 2 ----
    ln2_kernel<<<R_, 128>>>(out, ra1, rb1, a0, b0);
    gemm_qkv_kernel<<<gQKV, 256>>>(wq, bq, wk, bk, wv, bv);
    flash_kernel<<<gFLA, 256, FLASH_SMEM_BYTES>>>();
    gemm_out_kernel<<<gOUT, 256>>>(wo, bo, out, out);
}

// round 7
// speedup vs baseline: 7.6377x; 7.6377x over previous
#include <cuda_runtime.h>
#include <cuda_bf16.h>
#include <math.h>

#define B_  2
#define S_  4096
#define D_  384
#define H_  6
#define DK  64
#define R_  (B_*S_)
#define EPS 1e-6f
#define LDS 72    // smem row stride (bf16 elems): 144B rows -> conflict-free ldmatrix

// ---------------- scratch (device globals; no allocation allowed) ----------
__device__ __nv_bfloat16 g_zb[R_ * D_];                 // double-LN output (bf16)
__device__ __nv_bfloat16 g_q[B_ * H_ * S_ * DK];        // pre-scaled by 0.125
__device__ __nv_bfloat16 g_k[B_ * H_ * S_ * DK];
__device__ __nv_bfloat16 g_v[B_ * H_ * S_ * DK];
__device__ __nv_bfloat16 g_ob[R_ * D_];                 // attention output (bf16)
__device__ __nv_bfloat16 g_wb[4 * D_ * D_];             // wq|wk|wv|wo in bf16

// ---------------- mma / ldmatrix helpers ------------------------------------
__device__ __forceinline__ unsigned smem_u32(const void* p) {
    return (unsigned)__cvta_generic_to_shared(p);
}
__device__ __forceinline__ void ldm_x4(unsigned r[4], const void* p) {
    unsigned a = smem_u32(p);
    asm volatile("ldmatrix.sync.aligned.m8n8.x4.shared.b16 {%0,%1,%2,%3}, [%4];"
                 : "=r"(r[0]), "=r"(r[1]), "=r"(r[2]), "=r"(r[3]) : "r"(a));
}
__device__ __forceinline__ void ldm_x4_t(unsigned r[4], const void* p) {
    unsigned a = smem_u32(p);
    asm volatile("ldmatrix.sync.aligned.m8n8.x4.trans.shared.b16 {%0,%1,%2,%3}, [%4];"
                 : "=r"(r[0]), "=r"(r[1]), "=r"(r[2]), "=r"(r[3]) : "r"(a));
}
__device__ __forceinline__ void mma_bf16(float c[4], const unsigned a[4],
                                         unsigned b0, unsigned b1) {
    asm volatile("mma.sync.aligned.m16n8k16.row.col.f32.bf16.bf16.f32 "
                 "{%0,%1,%2,%3}, {%4,%5,%6,%7}, {%8,%9}, {%0,%1,%2,%3};"
                 : "+f"(c[0]), "+f"(c[1]), "+f"(c[2]), "+f"(c[3])
                 : "r"(a[0]), "r"(a[1]), "r"(a[2]), "r"(a[3]), "r"(b0), "r"(b1));
}
// pack two f32 into bf16x2: low half = lo, high half = hi
__device__ __forceinline__ unsigned pack_bf16(float lo, float hi) {
    unsigned d;
    asm("cvt.rn.bf16x2.f32 %0, %1, %2;" : "=r"(d) : "f"(hi), "f"(lo));
    return d;
}

// ---------------- weight conversion ------------------------------------------
__global__ __launch_bounds__(256) void convw_kernel(
    const float* __restrict__ wq, const float* __restrict__ wk,
    const float* __restrict__ wv, const float* __restrict__ wo)
{
    const float* src = (blockIdx.y == 0) ? wq : (blockIdx.y == 1) ? wk
                     : (blockIdx.y == 2) ? wv : wo;
    __nv_bfloat16* dst = g_wb + (size_t)blockIdx.y * D_ * D_;
    int i = (blockIdx.x * 256 + threadIdx.x) * 4;
    float4 v = *(const float4*)(src + i);
    *(unsigned*)(dst + i)     = pack_bf16(v.x, v.y);
    *(unsigned*)(dst + i + 2) = pack_bf16(v.z, v.w);
}

// ---------------- block reduction (128 threads) ------------------------------
__device__ __forceinline__ float blockSum(float v, float* sh) {
    int tid = threadIdx.x;
#pragma unroll
    for (int o = 16; o > 0; o >>= 1) v += __shfl_xor_sync(0xffffffffu, v, o);
    __syncthreads();
    if ((tid & 31) == 0) sh[tid >> 5] = v;
    __syncthreads();
    return sh[0] + sh[1] + sh[2] + sh[3];
}

// ---------------- fused double LayerNorm (fp32 in, bf16 out) ------------------
__global__ __launch_bounds__(128) void ln2_kernel(
    const float* __restrict__ x,
    const float* __restrict__ ra, const float* __restrict__ rb,
    const float* __restrict__ a0, const float* __restrict__ b0)
{
    __shared__ float sh[4];
    int row = blockIdx.x;
    int tid = threadIdx.x;
    const float* xr = x + (size_t)row * D_;

    float v[3];
#pragma unroll
    for (int c = 0; c < 3; c++) v[c] = xr[tid + 128 * c];

    float s = blockSum(v[0] + v[1] + v[2], sh);
    float mean = s * (1.0f / D_);
    float sq = 0.f;
#pragma unroll
    for (int c = 0; c < 3; c++) { float d = v[c] - mean; sq += d * d; }
    sq = blockSum(sq, sh);
    float inv = 1.0f / (sqrtf(sq * (1.0f / (D_ - 1))) + EPS);

    float y[3];
#pragma unroll
    for (int c = 0; c < 3; c++) {
        int i = tid + 128 * c;
        y[c] = ra[i] * (v[c] - mean) * inv + rb[i];
    }

    s = blockSum(y[0] + y[1] + y[2], sh);
    mean = s * (1.0f / D_);
    sq = 0.f;
#pragma unroll
    for (int c = 0; c < 3; c++) { float d = y[c] - mean; sq += d * d; }
    sq = blockSum(sq, sh);
    inv = 1.0f / (sqrtf(sq * (1.0f / (D_ - 1))) + EPS);

    __nv_bfloat16* zr = g_zb + (size_t)row * D_;
#pragma unroll
    for (int c = 0; c < 3; c++) {
        int i = tid + 128 * c;
        zr[i] = __float2bfloat16(a0[i] * (y[c] - mean) * inv + b0[i]);
    }
}

// ---------------- QKV projection (bf16 tensor mma) ----------------------------
// grid (R_/128, 18), 256 threads. Tile 128M x 64N, BK=64.
__global__ __launch_bounds__(256) void mma_qkv_kernel(
    const float* __restrict__ bq, const float* __restrict__ bk,
    const float* __restrict__ bv)
{
    __shared__ __nv_bfloat16 As[128 * LDS];
    __shared__ __nv_bfloat16 Bs[64 * LDS];

    int tid = threadIdx.x, warp = tid >> 5, lane = tid & 31;
    int g = lane >> 2, tig = lane & 3;
    int m0 = blockIdx.x * 128;
    int ntile = blockIdx.y;              // 0..17
    int which = ntile / 6;
    int h = ntile - which * 6;
    const __nv_bfloat16* W = g_wb + (size_t)which * (D_ * D_) + (size_t)h * 64 * D_;
    const float* bias = ((which == 0) ? bq : (which == 1) ? bk : bv) + h * 64;
    __nv_bfloat16* Out = (which == 0) ? g_q : (which == 1) ? g_k : g_v;

    int arow = tid >> 3, achk = tid & 7;
    uint4 ap[4], bp[2];

#pragma unroll
    for (int j = 0; j < 4; j++)
        ap[j] = *(const uint4*)(g_zb + (size_t)(m0 + arow + j * 32) * D_ + achk * 8);
#pragma unroll
    for (int j = 0; j < 2; j++)
        bp[j] = *(const uint4*)(W + (size_t)(arow + j * 32) * D_ + achk * 8);

    float acc[2][4][4] = {};
    int arow_sel = ((lane & 8) ? 8 : 0) + (lane & 7);
    int acol_sel = ((lane & 16) ? 8 : 0);
    int brow_sel = ((lane & 16) ? 8 : 0) + (lane & 7);
    int bcol_sel = ((lane & 8) ? 8 : 0);
    int mbase = (warp >> 1) * 32;
    int nbase = (warp & 1) * 32;

    for (int kc = 0; kc < 6; kc++) {
        __syncthreads();
#pragma unroll
        for (int j = 0; j < 4; j++) *(uint4*)&As[(arow + j * 32) * LDS + achk * 8] = ap[j];
#pragma unroll
        for (int j = 0; j < 2; j++) *(uint4*)&Bs[(arow + j * 32) * LDS + achk * 8] = bp[j];
        __syncthreads();
        if (kc < 5) {
            int k0 = (kc + 1) * 64;
#pragma unroll
            for (int j = 0; j < 4; j++)
                ap[j] = *(const uint4*)(g_zb + (size_t)(m0 + arow + j * 32) * D_ + k0 + achk * 8);
#pragma unroll
            for (int j = 0; j < 2; j++)
                bp[j] = *(const uint4*)(W + (size_t)(arow + j * 32) * D_ + k0 + achk * 8);
        }
#pragma unroll
        for (int ks = 0; ks < 4; ks++) {
            unsigned af[2][4], bf0[4], bf1[4];
            ldm_x4(af[0], &As[(mbase + arow_sel) * LDS + ks * 16 + acol_sel]);
            ldm_x4(af[1], &As[(mbase + 16 + arow_sel) * LDS + ks * 16 + acol_sel]);
            ldm_x4(bf0, &Bs[(nbase + brow_sel) * LDS + ks * 16 + bcol_sel]);
            ldm_x4(bf1, &Bs[(nbase + 16 + brow_sel) * LDS + ks * 16 + bcol_sel]);
#pragma unroll
            for (int mi = 0; mi < 2; mi++) {
                mma_bf16(acc[mi][0], af[mi], bf0[0], bf0[1]);
                mma_bf16(acc[mi][1], af[mi], bf0[2], bf0[3]);
                mma_bf16(acc[mi][2], af[mi], bf1[0], bf1[1]);
                mma_bf16(acc[mi][3], af[mi], bf1[2], bf1[3]);
            }
        }
    }

    float qs = (which == 0) ? 0.125f : 1.0f;   // fold 1/sqrt(dk) into q
#pragma unroll
    for (int nb = 0; nb < 4; nb++) {
        int j = nbase + nb * 8 + 2 * tig;
        float b0v = bias[j], b1v = bias[j + 1];
#pragma unroll
        for (int mi = 0; mi < 2; mi++) {
            int row = m0 + mbase + mi * 16 + g;
            int bidx = row >> 12;
            int s = row & (S_ - 1);
            __nv_bfloat16* po = Out + (((size_t)(bidx * H_ + h)) * S_ + s) * DK + j;
            *(unsigned*)po            = pack_bf16((acc[mi][nb][0] + b0v) * qs,
                                                  (acc[mi][nb][1] + b1v) * qs);
            *(unsigned*)(po + 8 * DK) = pack_bf16((acc[mi][nb][2] + b0v) * qs,
                                                  (acc[mi][nb][3] + b1v) * qs);
        }
    }
}

// ---------------- output projection + residual (bf16 mma, fp32 out) -----------
__global__ __launch_bounds__(256) void mma_out_kernel(
    const float* __restrict__ bo, const float* __restrict__ xres,
    float* __restrict__ out)
{
    __shared__ __nv_bfloat16 As[128 * LDS];
    __shared__ __nv_bfloat16 Bs[64 * LDS];

    int tid = threadIdx.x, warp = tid >> 5, lane = tid & 31;
    int g = lane >> 2, tig = lane & 3;
    int m0 = blockIdx.x * 128;
    int n0 = blockIdx.y * 64;
    const __nv_bfloat16* W = g_wb + (size_t)3 * D_ * D_ + (size_t)n0 * D_;

    int arow = tid >> 3, achk = tid & 7;
    uint4 ap[4], bp[2];
#pragma unroll
    for (int j = 0; j < 4; j++)
        ap[j] = *(const uint4*)(g_ob + (size_t)(m0 + arow + j * 32) * D_ + achk * 8);
#pragma unroll
    for (int j = 0; j < 2; j++)
        bp[j] = *(const uint4*)(W + (size_t)(arow + j * 32) * D_ + achk * 8);

    float acc[2][4][4] = {};
    int arow_sel = ((lane & 8) ? 8 : 0) + (lane & 7);
    int acol_sel = ((lane & 16) ? 8 : 0);
    int brow_sel = ((lane & 16) ? 8 : 0) + (lane & 7);
    int bcol_sel = ((lane & 8) ? 8 : 0);
    int mbase = (warp >> 1) * 32;
    int nbase = (warp & 1) * 32;

    for (int kc = 0; kc < 6; kc++) {
        __syncthreads();
#pragma unroll
        for (int j = 0; j < 4; j++) *(uint4*)&As[(arow + j * 32) * LDS + achk * 8] = ap[j];
#pragma unroll
        for (int j = 0; j < 2; j++) *(uint4*)&Bs[(arow + j * 32) * LDS + achk * 8] = bp[j];
        __syncthreads();
        if (kc < 5) {
            int k0 = (kc + 1) * 64;
#pragma unroll
            for (int j = 0; j < 4; j++)
                ap[j] = *(const uint4*)(g_ob + (size_t)(m0 + arow + j * 32) * D_ + k0 + achk * 8);
#pragma unroll
            for (int j = 0; j < 2; j++)
                bp[j] = *(const uint4*)(W + (size_t)(arow + j * 32) * D_ + k0 + achk * 8);
        }
#pragma unroll
        for (int ks = 0; ks < 4; ks++) {
            unsigned af[2][4], bf0[4], bf1[4];
            ldm_x4(af[0], &As[(mbase + arow_sel) * LDS + ks * 16 + acol_sel]);
            ldm_x4(af[1], &As[(mbase + 16 + arow_sel) * LDS + ks * 16 + acol_sel]);
            ldm_x4(bf0, &Bs[(nbase + brow_sel) * LDS + ks * 16 + bcol_sel]);
            ldm_x4(bf1, &Bs[(nbase + 16 + brow_sel) * LDS + ks * 16 + bcol_sel]);
#pragma unroll
            for (int mi = 0; mi < 2; mi++) {
                mma_bf16(acc[mi][0], af[mi], bf0[0], bf0[1]);
                mma_bf16(acc[mi][1], af[mi], bf0[2], bf0[3]);
                mma_bf16(acc[mi][2], af[mi], bf1[0], bf1[1]);
                mma_bf16(acc[mi][3], af[mi], bf1[2], bf1[3]);
            }
        }
    }

#pragma unroll
    for (int nb = 0; nb < 4; nb++) {
        int col = n0 + nbase + nb * 8 + 2 * tig;
        float b0v = bo[col], b1v = bo[col + 1];
#pragma unroll
        for (int mi = 0; mi < 2; mi++) {
            int row = m0 + mbase + mi * 16 + g;
            float2 x0 = *(const float2*)(xres + (size_t)row * D_ + col);
            float2 x1 = *(const float2*)(xres + (size_t)(row + 8) * D_ + col);
            float2 o0, o1;
            o0.x = x0.x + acc[mi][nb][0] + b0v;
            o0.y = x0.y + acc[mi][nb][1] + b1v;
            o1.x = x1.x + acc[mi][nb][2] + b0v;
            o1.y = x1.y + acc[mi][nb][3] + b1v;
            *(float2*)(out + (size_t)row * D_ + col)       = o0;
            *(float2*)(out + (size_t)(row + 8) * D_ + col) = o1;
        }
    }
}

// ---------------- flash attention (bf16 tensor mma) ----------------------------
// grid (S_/128, B_*H_), 256 threads (8 warps). Warp w -> queries [w*16, w*16+16).
__global__ __launch_bounds__(256) void flash_mma_kernel()
{
    __shared__ __nv_bfloat16 Qs[128 * LDS];
    __shared__ __nv_bfloat16 Ks[64 * LDS];
    __shared__ __nv_bfloat16 Vs[64 * LDS];

    int tid = threadIdx.x, warp = tid >> 5, lane = tid & 31;
    int g = lane >> 2, tig = lane & 3;
    int bh = blockIdx.y, qb = blockIdx.x;

    const __nv_bfloat16* Qg = g_q + ((size_t)bh * S_ + qb * 128) * DK;
    const __nv_bfloat16* Kg = g_k + (size_t)bh * S_ * DK;
    const __nv_bfloat16* Vg = g_v + (size_t)bh * S_ * DK;

    // load Q tile + first K/V tile
#pragma unroll
    for (int j = 0; j < 4; j++) {
        int i = tid + j * 256;
        int r = i >> 3, c = i & 7;
        *(uint4*)&Qs[r * LDS + c * 8] = *(const uint4*)(Qg + r * DK + c * 8);
    }
    int brow = tid >> 3, bchk = tid & 7;
#pragma unroll
    for (int j = 0; j < 2; j++) {
        int r = brow + j * 32;
        *(uint4*)&Ks[r * LDS + bchk * 8] = *(const uint4*)(Kg + r * DK + bchk * 8);
        *(uint4*)&Vs[r * LDS + bchk * 8] = *(const uint4*)(Vg + r * DK + bchk * 8);
    }
    __syncthreads();

    // Q fragments, kept in registers for the whole kernel
    unsigned qf[4][4];
    {
        int row = warp * 16 + ((lane & 8) ? 8 : 0) + (lane & 7);
        int csel = ((lane & 16) ? 8 : 0);
#pragma unroll
        for (int kd = 0; kd < 4; kd++)
            ldm_x4(qf[kd], &Qs[row * LDS + kd * 16 + csel]);
    }

    float m0 = -1e30f, m1 = -1e30f, l0 = 0.f, l1 = 0.f;
    float fo[8][4] = {};
    uint4 kp[2], vp[2];

    int krow_sel = ((lane & 16) ? 8 : 0) + (lane & 7);   // B-frag (K, non-trans)
    int kcol_sel = ((lane & 8) ? 8 : 0);
    int vrow_sel = ((lane & 8) ? 8 : 0) + (lane & 7);    // B-frag (V, trans)
    int vcol_sel = ((lane & 16) ? 8 : 0);

    for (int kt = 0; kt < S_ / 64; kt++) {
        if (kt + 1 < S_ / 64) {
            const __nv_bfloat16* Kn = Kg + (size_t)(kt + 1) * 64 * DK;
            const __nv_bfloat16* Vn = Vg + (size_t)(kt + 1) * 64 * DK;
#pragma unroll
            for (int j = 0; j < 2; j++) {
                int r = brow + j * 32;
                kp[j] = *(const uint4*)(Kn + r * DK + bchk * 8);
                vp[j] = *(const uint4*)(Vn + r * DK + bchk * 8);
            }
        }

        // S = Q K^T (q pre-scaled by 1/8)
        float sa[8][4] = {};
#pragma unroll
        for (int kd = 0; kd < 4; kd++) {
#pragma unroll
            for (int nb2 = 0; nb2 < 4; nb2++) {
                unsigned bk[4];
                ldm_x4(bk, &Ks[(nb2 * 16 + krow_sel) * LDS + kd * 16 + kcol_sel]);
                mma_bf16(sa[2 * nb2],     qf[kd], bk[0], bk[1]);
                mma_bf16(sa[2 * nb2 + 1], qf[kd], bk[2], bk[3]);
            }
        }

        // online softmax (rows g and g+8)
        float mx0 = -1e30f, mx1 = -1e30f;
#pragma unroll
        for (int nb = 0; nb < 8; nb++) {
            mx0 = fmaxf(mx0, fmaxf(sa[nb][0], sa[nb][1]));
            mx1 = fmaxf(mx1, fmaxf(sa[nb][2], sa[nb][3]));
        }
        mx0 = fmaxf(mx0, __shfl_xor_sync(0xffffffffu, mx0, 1));
        mx0 = fmaxf(mx0, __shfl_xor_sync(0xffffffffu, mx0, 2));
        mx1 = fmaxf(mx1, __shfl_xor_sync(0xffffffffu, mx1, 1));
        mx1 = fmaxf(mx1, __shfl_xor_sync(0xffffffffu, mx1, 2));
        float mn0 = fmaxf(m0, mx0), mn1 = fmaxf(m1, mx1);
        float sc0 = __expf(m0 - mn0), sc1 = __expf(m1 - mn1);
        m0 = mn0; m1 = mn1;
        float s0 = 0.f, s1 = 0.f;
#pragma unroll
        for (int nb = 0; nb < 8; nb++) {
            sa[nb][0] = __expf(sa[nb][0] - m0);
            sa[nb][1] = __expf(sa[nb][1] - m0);
            sa[nb][2] = __expf(sa[nb][2] - m1);
            sa[nb][3] = __expf(sa[nb][3] - m1);
            s0 += sa[nb][0] + sa[nb][1];
            s1 += sa[nb][2] + sa[nb][3];
        }
        s0 += __shfl_xor_sync(0xffffffffu, s0, 1);
        s0 += __shfl_xor_sync(0xffffffffu, s0, 2);
        s1 += __shfl_xor_sync(0xffffffffu, s1, 1);
        s1 += __shfl_xor_sync(0xffffffffu, s1, 2);
        l0 = l0 * sc0 + s0;
        l1 = l1 * sc1 + s1;
#pragma unroll
        for (int nb = 0; nb < 8; nb++) {
            fo[nb][0] *= sc0; fo[nb][1] *= sc0;
            fo[nb][2] *= sc1; fo[nb][3] *= sc1;
        }

        // O += P V  (P re-packed from S accumulators, registers only)
#pragma unroll
        for (int kk = 0; kk < 4; kk++) {
            unsigned aP[4];
            aP[0] = pack_bf16(sa[2 * kk][0],     sa[2 * kk][1]);
            aP[1] = pack_bf16(sa[2 * kk][2],     sa[2 * kk][3]);
            aP[2] = pack_bf16(sa[2 * kk + 1][0], sa[2 * kk + 1][1]);
            aP[3] = pack_bf16(sa[2 * kk + 1][2], sa[2 * kk + 1][3]);
#pragma unroll
            for (int db2 = 0; db2 < 4; db2++) {
                unsigned bv[4];
                ldm_x4_t(bv, &Vs[(kk * 16 + vrow_sel) * LDS + db2 * 16 + vcol_sel]);
                mma_bf16(fo[2 * db2],     aP, bv[0], bv[1]);
                mma_bf16(fo[2 * db2 + 1], aP, bv[2], bv[3]);
            }
        }

        __syncthreads();
        if (kt + 1 < S_ / 64) {
#pragma unroll
            for (int j = 0; j < 2; j++) {
                int r = brow + j * 32;
                *(uint4*)&Ks[r * LDS + bchk * 8] = kp[j];
                *(uint4*)&Vs[r * LDS + bchk * 8] = vp[j];
            }
        }
        __syncthreads();
    }

    // epilogue: O /= l, write bf16 to g_ob[b, s, h*64 + d]
    float inv0 = 1.0f / l0, inv1 = 1.0f / l1;
    int b = bh / H_, h = bh - b * H_;
    int row0 = qb * 128 + warp * 16 + g;
    __nv_bfloat16* O0 = g_ob + ((size_t)(b * S_) + row0) * D_ + h * DK;
    __nv_bfloat16* O1 = O0 + 8 * D_;
#pragma unroll
    for (int db = 0; db < 8; db++) {
        int c = db * 8 + 2 * tig;
        *(unsigned*)(O0 + c) = pack_bf16(fo[db][0] * inv0, fo[db][1] * inv0);
        *(unsigned*)(O1 + c) = pack_bf16(fo[db][2] * inv1, fo[db][3] * inv1);
    }
}

// ---------------- host launcher ------------------------------------------------
extern "C" void kernel_launch(void* const* d_in, const int* in_sizes, int n_in,
                              void* d_out, int out_size)
{
    (void)in_sizes; (void)n_in; (void)out_size;
    const float* x   = (const float*)d_in[0];
    const float* a0  = (const float*)d_in[1];
    const float* b0  = (const float*)d_in[2];
    const float* ra0 = (const float*)d_in[3];
    const float* rb0 = (const float*)d_in[4];
    const float* ra1 = (const float*)d_in[5];
    const float* rb1 = (const float*)d_in[6];
    const float* wq  = (const float*)d_in[7];
    const float* bq  = (const float*)d_in[8];
    const float* wk  = (const float*)d_in[9];
    const float* bk  = (const float*)d_in[10];
    const float* wv  = (const float*)d_in[11];
    const float* bv  = (const float*)d_in[12];
    const float* wo  = (const float*)d_in[13];
    const float* bo  = (const float*)d_in[14];
    float* out = (float*)d_out;

    dim3 gQKV(R_ / 128, 18);
    dim3 gOUT(R_ / 128, 6);
    dim3 gFLA(S_ / 128, B_ * H_);

    convw_kernel<<<dim3(144, 4), 256>>>(wq, wk, wv, wo);

    // ---- block 1 ----
    ln2_kernel<<<R_, 128>>>(x, ra0, rb0, a0, b0);
    mma_qkv_kernel<<<gQKV, 256>>>(bq, bk, bv);
    flash_mma_kernel<<<gFLA, 256>>>();
    mma_out_kernel<<<gOUT, 256>>>(bo, x, out);

    // ---- block 2 ----
    ln2_kernel<<<R_, 128>>>(out, ra1, rb1, a0, b0);
    mma_qkv_kernel<<<gQKV, 256>>>(bq, bk, bv);
    flash_mma_kernel<<<gFLA, 256>>>();
    mma_out_kernel<<<gOUT, 256>>>(bo, out, out);
}